// round 6
// baseline (speedup 1.0000x reference)
#include <cuda_runtime.h>
#include <cstdint>

// Delta modulation encoder: x (64, 8, 131072) f32 -> spikes {-1,0,+1} f32.
// 512 sequences of T=131072, thr = 0.1f. Output bit-exact vs reference.
//
// pass1:  parallel speculative pass (warm-up 512 steps). Writes spikes as
//         packed int8 words + per-128-step-block (state, margin) records.
// passB:  one exact chain per sequence. Per block: if recorded margin exceeds
//         |S - r0| + SLACK, all decisions provably match -> replay S from the
//         spike bytes (1 FFMA per step, 4 cy chain). Else exact recompute of
//         the 128 steps from x and rewrite of the spike bytes.
// decode: packed bytes -> float spikes, fully coalesced.

#define DM_T      131072
#define DM_NSEQ   512
#define DM_L      2048
#define DM_W      512
#define DM_NCH    (DM_T / DM_L)          /* 64    */
#define DM_NCHK   (DM_NSEQ * DM_NCH)     /* 32768 */
#define DM_B      128                    /* verification block   */
#define DM_NBS    (DM_T / DM_B)          /* 1024 blocks per seq  */
#define DM_THR    0.1f
#define DM_SLACK  1e-4f                  /* > 128*ulp(6) drift + sub rounding */

__device__ unsigned g_sd [DM_NSEQ * DM_T / 4];   // packed int8 spikes (64 MB)
__device__ float2   g_rec[DM_NSEQ * DM_NBS];     // (state@blockstart, margin)

// Reference step, bitwise: e = fl(x-r); pos=(e>thr); neg=(e<-thr);
// r = fl(r + spike*thr)  (spike*thr exact).
__device__ __forceinline__ unsigned dm_step_m(float xx, float& r, float& m) {
    float e = xx - r;
    bool pos = e >  DM_THR;
    bool neg = e < -DM_THR;
    r += pos ? DM_THR : (neg ? -DM_THR : 0.0f);
    m = fminf(m, fminf(fabsf(e - DM_THR), fabsf(e + DM_THR)));
    return pos ? 1u : (neg ? 0xFFu : 0u);
}
__device__ __forceinline__ unsigned dm_step_f(float xx, float& r) {
    float e = xx - r;
    bool pos = e >  DM_THR;
    bool neg = e < -DM_THR;
    r += pos ? DM_THR : (neg ? -DM_THR : 0.0f);
    return pos ? 1u : (neg ? 0xFFu : 0u);
}
__device__ __forceinline__ void dm_step_w(float xx, float& r) {
    float e = xx - r;
    bool pos = e >  DM_THR;
    bool neg = e < -DM_THR;
    r += pos ? DM_THR : (neg ? -DM_THR : 0.0f);
}

// ---------------------------------------------------------------------------
// Pass 1: one thread per 2048-chunk. Warm-up, then 16 blocks of 128 steps:
// emit packed spike bytes (uint4 = 16 spikes) and (state, margin) records.
// ---------------------------------------------------------------------------
__global__ void __launch_bounds__(128) dm_pass1(const float* __restrict__ x) {
    const int id  = blockIdx.x * 128 + threadIdx.x;      // grid sized exactly
    const int seq = id / DM_NCH;
    const int c   = id % DM_NCH;
    const size_t cbase = (size_t)seq * DM_T + (size_t)c * DM_L;

    float r = 0.0f;

    if (c > 0) {                                         // warm-up, no output
        const float4* __restrict__ wv =
            reinterpret_cast<const float4*>(x + cbase - DM_W);
#pragma unroll 4
        for (int g = 0; g < DM_W / 4; ++g) {
            float4 a = __ldg(wv + g);
            dm_step_w(a.x, r); dm_step_w(a.y, r);
            dm_step_w(a.z, r); dm_step_w(a.w, r);
        }
    }

    const float4* __restrict__ xv  = reinterpret_cast<const float4*>(x + cbase);
    uint4*        __restrict__ sdv = reinterpret_cast<uint4*>(g_sd) + cbase / 16;
    float2*       __restrict__ rp  = g_rec + cbase / DM_B;

    for (int b = 0; b < DM_L / DM_B; ++b) {              // 16 blocks
        float r0 = r, m = 1e30f;
#pragma unroll 2
        for (int g = 0; g < DM_B / 16; ++g) {            // 8 x 16 steps
            unsigned w[4];
#pragma unroll
            for (int q = 0; q < 4; ++q) {
                float4 a = __ldcs(xv + b * 32 + g * 4 + q);
                unsigned b0 = dm_step_m(a.x, r, m);
                unsigned b1 = dm_step_m(a.y, r, m);
                unsigned b2 = dm_step_m(a.z, r, m);
                unsigned b3 = dm_step_m(a.w, r, m);
                w[q] = b0 | (b1 << 8) | (b2 << 16) | (b3 << 24);
            }
            __stcs(sdv + b * 8 + g, make_uint4(w[0], w[1], w[2], w[3]));
        }
        rp[b] = make_float2(r0, m);
    }
}

// ---------------------------------------------------------------------------
// Pass B: one sequence per block (lane 0 active), 512 blocks over the SMs.
// Verified blocks: replay S from spike bytes (FFMA chain, 4 cy/step).
// Unverified: exact recompute from x + rewrite of spike bytes.
// ---------------------------------------------------------------------------
__global__ void __launch_bounds__(32) dm_passB(const float* __restrict__ x) {
    if (threadIdx.x != 0) return;
    const int seq = blockIdx.x;

    const uint4*  __restrict__ spv =
        reinterpret_cast<const uint4*>(g_sd) + (size_t)seq * (DM_T / 16);
    uint4*        __restrict__ spw =
        reinterpret_cast<uint4*>(g_sd) + (size_t)seq * (DM_T / 16);
    const float2* __restrict__ rec = g_rec + (size_t)seq * DM_NBS;

    float S = 0.0f;

    uint4 buf[8];
#pragma unroll
    for (int k = 0; k < 8; ++k) buf[k] = __ldg(spv + k);
    float2 rc = __ldg(rec + 0);

    for (int j = 0; j < DM_NBS; ++j) {
        // prefetch next block's bytes + record (independent of the chain)
        uint4 nbuf[8]; float2 nrc = rc;
        if (j + 1 < DM_NBS) {
#pragma unroll
            for (int k = 0; k < 8; ++k) nbuf[k] = __ldg(spv + (j + 1) * 8 + k);
            nrc = __ldg(rec + j + 1);
        }

        const float diff = fabsf(S - rc.x);
        if (rc.y > diff + DM_SLACK) {
            // provably exact replay: S += spike*thr, 128 serial FFMAs
#pragma unroll
            for (int k = 0; k < 8; ++k) {
                unsigned ws[4] = {buf[k].x, buf[k].y, buf[k].z, buf[k].w};
#pragma unroll
                for (int q = 0; q < 4; ++q) {
                    unsigned w = ws[q];
                    S += (float)(signed char)(w)       * DM_THR;
                    S += (float)(signed char)(w >> 8)  * DM_THR;
                    S += (float)(signed char)(w >> 16) * DM_THR;
                    S += (float)(signed char)(w >> 24) * DM_THR;
                }
            }
        } else {
            // exact recompute of this 128-step block; rewrite spike bytes
            const float4* __restrict__ xb = reinterpret_cast<const float4*>(
                x + (size_t)seq * DM_T + (size_t)j * DM_B);
#pragma unroll 2
            for (int g = 0; g < 8; ++g) {
                unsigned w[4];
#pragma unroll
                for (int q = 0; q < 4; ++q) {
                    float4 a = __ldg(xb + g * 4 + q);
                    unsigned b0 = dm_step_f(a.x, S);
                    unsigned b1 = dm_step_f(a.y, S);
                    unsigned b2 = dm_step_f(a.z, S);
                    unsigned b3 = dm_step_f(a.w, S);
                    w[q] = b0 | (b1 << 8) | (b2 << 16) | (b3 << 24);
                }
                spw[j * 8 + g] = make_uint4(w[0], w[1], w[2], w[3]);
            }
        }

#pragma unroll
        for (int k = 0; k < 8; ++k) buf[k] = nbuf[k];
        rc = nrc;
    }
}

// ---------------------------------------------------------------------------
// Decode: packed bytes -> float spikes. One uint32 word (4 spikes) per
// thread: coalesced 128B reads and 512B float4 writes per warp.
// ---------------------------------------------------------------------------
__global__ void __launch_bounds__(256) dm_decode(float* __restrict__ out) {
    const size_t i = (size_t)blockIdx.x * 256 + threadIdx.x;
    const unsigned w = g_sd[i];
    float4 f;
    f.x = (float)(signed char)(w);
    f.y = (float)(signed char)(w >> 8);
    f.z = (float)(signed char)(w >> 16);
    f.w = (float)(signed char)(w >> 24);
    reinterpret_cast<float4*>(out)[i] = f;
}

// ---------------------------------------------------------------------------
extern "C" void kernel_launch(void* const* d_in, const int* in_sizes, int n_in,
                              void* d_out, int out_size) {
    const float* x = (const float*)d_in[0];
    float* out = (float*)d_out;
    (void)in_sizes; (void)n_in; (void)out_size;

    dm_pass1 <<<DM_NCHK / 128, 128>>>(x);
    dm_passB <<<DM_NSEQ, 32>>>(x);
    dm_decode<<<(DM_NSEQ * DM_T / 4) / 256, 256>>>(out);
}

// round 7
// speedup vs baseline: 1.0050x; 1.0050x over previous
#include <cuda_runtime.h>
#include <cstdint>

// Delta modulation encoder: x (64, 8, 131072) f32 -> spikes {-1,0,+1} f32.
// 512 sequences of T=131072, thr = 0.1f. Output bit-exact vs reference.
//
// pass1:  parallel speculative pass (warm-up 512 steps). Writes spikes as
//         packed int8 words + per-128-step-block (state, margin) records.
// passB:  one exact chain per sequence. Per block: if recorded margin exceeds
//         |S - r0| + SLACK, all decisions provably match -> replay S from the
//         spike bytes (1 FFMA per step, 4 cy chain). Else exact recompute of
//         the 128 steps from x and rewrite of the spike bytes.
// decode: packed bytes -> float spikes, fully coalesced.

#define DM_T      131072
#define DM_NSEQ   512
#define DM_L      2048
#define DM_W      512
#define DM_NCH    (DM_T / DM_L)          /* 64    */
#define DM_NCHK   (DM_NSEQ * DM_NCH)     /* 32768 */
#define DM_B      128                    /* verification block   */
#define DM_NBS    (DM_T / DM_B)          /* 1024 blocks per seq  */
#define DM_THR    0.1f
#define DM_SLACK  1e-4f                  /* > 128*ulp(6) drift + sub rounding */

__device__ unsigned g_sd [DM_NSEQ * DM_T / 4];   // packed int8 spikes (64 MB)
__device__ float2   g_rec[DM_NSEQ * DM_NBS];     // (state@blockstart, margin)

// Reference step, bitwise: e = fl(x-r); pos=(e>thr); neg=(e<-thr);
// r = fl(r + spike*thr)  (spike*thr exact).
__device__ __forceinline__ unsigned dm_step_m(float xx, float& r, float& m) {
    float e = xx - r;
    bool pos = e >  DM_THR;
    bool neg = e < -DM_THR;
    r += pos ? DM_THR : (neg ? -DM_THR : 0.0f);
    m = fminf(m, fminf(fabsf(e - DM_THR), fabsf(e + DM_THR)));
    return pos ? 1u : (neg ? 0xFFu : 0u);
}
__device__ __forceinline__ unsigned dm_step_f(float xx, float& r) {
    float e = xx - r;
    bool pos = e >  DM_THR;
    bool neg = e < -DM_THR;
    r += pos ? DM_THR : (neg ? -DM_THR : 0.0f);
    return pos ? 1u : (neg ? 0xFFu : 0u);
}
__device__ __forceinline__ void dm_step_w(float xx, float& r) {
    float e = xx - r;
    bool pos = e >  DM_THR;
    bool neg = e < -DM_THR;
    r += pos ? DM_THR : (neg ? -DM_THR : 0.0f);
}

// ---------------------------------------------------------------------------
// Pass 1: one thread per 2048-chunk. Warm-up, then 16 blocks of 128 steps:
// emit packed spike bytes (uint4 = 16 spikes) and (state, margin) records.
// ---------------------------------------------------------------------------
__global__ void __launch_bounds__(128) dm_pass1(const float* __restrict__ x) {
    const int id  = blockIdx.x * 128 + threadIdx.x;      // grid sized exactly
    const int seq = id / DM_NCH;
    const int c   = id % DM_NCH;
    const size_t cbase = (size_t)seq * DM_T + (size_t)c * DM_L;

    float r = 0.0f;

    if (c > 0) {                                         // warm-up, no output
        const float4* __restrict__ wv =
            reinterpret_cast<const float4*>(x + cbase - DM_W);
#pragma unroll 4
        for (int g = 0; g < DM_W / 4; ++g) {
            float4 a = __ldg(wv + g);
            dm_step_w(a.x, r); dm_step_w(a.y, r);
            dm_step_w(a.z, r); dm_step_w(a.w, r);
        }
    }

    const float4* __restrict__ xv  = reinterpret_cast<const float4*>(x + cbase);
    uint4*        __restrict__ sdv = reinterpret_cast<uint4*>(g_sd) + cbase / 16;
    float2*       __restrict__ rp  = g_rec + cbase / DM_B;

    for (int b = 0; b < DM_L / DM_B; ++b) {              // 16 blocks
        float r0 = r, m = 1e30f;
#pragma unroll 2
        for (int g = 0; g < DM_B / 16; ++g) {            // 8 x 16 steps
            unsigned w[4];
#pragma unroll
            for (int q = 0; q < 4; ++q) {
                float4 a = __ldcs(xv + b * 32 + g * 4 + q);
                unsigned b0 = dm_step_m(a.x, r, m);
                unsigned b1 = dm_step_m(a.y, r, m);
                unsigned b2 = dm_step_m(a.z, r, m);
                unsigned b3 = dm_step_m(a.w, r, m);
                w[q] = b0 | (b1 << 8) | (b2 << 16) | (b3 << 24);
            }
            __stcs(sdv + b * 8 + g, make_uint4(w[0], w[1], w[2], w[3]));
        }
        rp[b] = make_float2(r0, m);
    }
}

// ---------------------------------------------------------------------------
// Pass B: one sequence per block (lane 0 active), 512 blocks over the SMs.
// Verified blocks: replay S from spike bytes (FFMA chain, 4 cy/step).
// Unverified: exact recompute from x + rewrite of spike bytes.
// ---------------------------------------------------------------------------
__global__ void __launch_bounds__(32) dm_passB(const float* __restrict__ x) {
    if (threadIdx.x != 0) return;
    const int seq = blockIdx.x;

    const uint4*  __restrict__ spv =
        reinterpret_cast<const uint4*>(g_sd) + (size_t)seq * (DM_T / 16);
    uint4*        __restrict__ spw =
        reinterpret_cast<uint4*>(g_sd) + (size_t)seq * (DM_T / 16);
    const float2* __restrict__ rec = g_rec + (size_t)seq * DM_NBS;

    float S = 0.0f;

    uint4 buf[8];
#pragma unroll
    for (int k = 0; k < 8; ++k) buf[k] = __ldg(spv + k);
    float2 rc = __ldg(rec + 0);

    for (int j = 0; j < DM_NBS; ++j) {
        // prefetch next block's bytes + record (independent of the chain)
        uint4 nbuf[8]; float2 nrc = rc;
        if (j + 1 < DM_NBS) {
#pragma unroll
            for (int k = 0; k < 8; ++k) nbuf[k] = __ldg(spv + (j + 1) * 8 + k);
            nrc = __ldg(rec + j + 1);
        }

        const float diff = fabsf(S - rc.x);
        if (rc.y > diff + DM_SLACK) {
            // provably exact replay: S += spike*thr, 128 serial FFMAs
#pragma unroll
            for (int k = 0; k < 8; ++k) {
                unsigned ws[4] = {buf[k].x, buf[k].y, buf[k].z, buf[k].w};
#pragma unroll
                for (int q = 0; q < 4; ++q) {
                    unsigned w = ws[q];
                    S += (float)(signed char)(w)       * DM_THR;
                    S += (float)(signed char)(w >> 8)  * DM_THR;
                    S += (float)(signed char)(w >> 16) * DM_THR;
                    S += (float)(signed char)(w >> 24) * DM_THR;
                }
            }
        } else {
            // exact recompute of this 128-step block; rewrite spike bytes
            const float4* __restrict__ xb = reinterpret_cast<const float4*>(
                x + (size_t)seq * DM_T + (size_t)j * DM_B);
#pragma unroll 2
            for (int g = 0; g < 8; ++g) {
                unsigned w[4];
#pragma unroll
                for (int q = 0; q < 4; ++q) {
                    float4 a = __ldg(xb + g * 4 + q);
                    unsigned b0 = dm_step_f(a.x, S);
                    unsigned b1 = dm_step_f(a.y, S);
                    unsigned b2 = dm_step_f(a.z, S);
                    unsigned b3 = dm_step_f(a.w, S);
                    w[q] = b0 | (b1 << 8) | (b2 << 16) | (b3 << 24);
                }
                spw[j * 8 + g] = make_uint4(w[0], w[1], w[2], w[3]);
            }
        }

#pragma unroll
        for (int k = 0; k < 8; ++k) buf[k] = nbuf[k];
        rc = nrc;
    }
}

// ---------------------------------------------------------------------------
// Decode: packed bytes -> float spikes. One uint32 word (4 spikes) per
// thread: coalesced 128B reads and 512B float4 writes per warp.
// ---------------------------------------------------------------------------
__global__ void __launch_bounds__(256) dm_decode(float* __restrict__ out) {
    const size_t i = (size_t)blockIdx.x * 256 + threadIdx.x;
    const unsigned w = g_sd[i];
    float4 f;
    f.x = (float)(signed char)(w);
    f.y = (float)(signed char)(w >> 8);
    f.z = (float)(signed char)(w >> 16);
    f.w = (float)(signed char)(w >> 24);
    reinterpret_cast<float4*>(out)[i] = f;
}

// ---------------------------------------------------------------------------
extern "C" void kernel_launch(void* const* d_in, const int* in_sizes, int n_in,
                              void* d_out, int out_size) {
    const float* x = (const float*)d_in[0];
    float* out = (float*)d_out;
    (void)in_sizes; (void)n_in; (void)out_size;

    dm_pass1 <<<DM_NCHK / 128, 128>>>(x);
    dm_passB <<<DM_NSEQ, 32>>>(x);
    dm_decode<<<(DM_NSEQ * DM_T / 4) / 256, 256>>>(out);
}